// round 1
// baseline (speedup 1.0000x reference)
#include <cuda_runtime.h>
#include <math.h>

#define B_  16
#define L_  1024
#define D_  256
#define H_  8
#define HD_ 32
#define NL_ 3
#define M_  (B_ * L_)   // 16384

// ---------------- scratch (no allocations allowed) ----------------
__device__ float g_x[M_ * D_];        // activations            (16 MB)
__device__ float g_qkv[M_ * 3 * D_];  // fused qkv              (50 MB)
__device__ float g_ao[M_ * D_];       // attention output       (16 MB)
__device__ float g_h1[M_ * D_];       // post-residual hidden   (16 MB)

// ---------------- embedding gather ----------------
__global__ void embed_kernel(const int* __restrict__ ut,
                             const float* __restrict__ emb,
                             float* __restrict__ x) {
    int row = blockIdx.x;
    int d = threadIdx.x;
    x[(size_t)row * D_ + d] = emb[(size_t)ut[row] * D_ + d];
}

// ---------------- generic GEMM: C[M,N] = A[M,K] @ W[N,K]^T + bias (+res) (relu) ----
// BM=128, BN=64, BK=16, 256 threads, 8x4 microtile per thread.
__global__ void __launch_bounds__(256) gemm_kernel(
    const float* __restrict__ A, const float* __restrict__ W,
    const float* __restrict__ bias, const float* __restrict__ res,
    float* __restrict__ C, int N, int K, int doRelu) {
    __shared__ float As[16][128];
    __shared__ float Bs[16][64];
    const int tid = threadIdx.x;
    const int tx = tid & 15;     // n-dir
    const int ty = tid >> 4;     // m-dir
    const int row0 = blockIdx.y * 128;
    const int col0 = blockIdx.x * 64;
    const int ar = tid >> 1, ac = (tid & 1) * 8;
    const int br = tid & 63, bc = (tid >> 6) * 4;

    float acc[8][4];
#pragma unroll
    for (int i = 0; i < 8; i++)
#pragma unroll
        for (int j = 0; j < 4; j++) acc[i][j] = 0.f;

    for (int kt = 0; kt < K; kt += 16) {
        const float* ap = A + (size_t)(row0 + ar) * K + kt + ac;
        float4 a0 = *(const float4*)ap;
        float4 a1 = *(const float4*)(ap + 4);
        As[ac + 0][ar] = a0.x; As[ac + 1][ar] = a0.y;
        As[ac + 2][ar] = a0.z; As[ac + 3][ar] = a0.w;
        As[ac + 4][ar] = a1.x; As[ac + 5][ar] = a1.y;
        As[ac + 6][ar] = a1.z; As[ac + 7][ar] = a1.w;
        const float* wp = W + (size_t)(col0 + br) * K + kt + bc;
        float4 b0 = *(const float4*)wp;
        Bs[bc + 0][br] = b0.x; Bs[bc + 1][br] = b0.y;
        Bs[bc + 2][br] = b0.z; Bs[bc + 3][br] = b0.w;
        __syncthreads();
#pragma unroll
        for (int kk = 0; kk < 16; kk++) {
            float a[8], bb[4];
            *(float4*)&a[0] = *(const float4*)&As[kk][ty * 8];
            *(float4*)&a[4] = *(const float4*)&As[kk][ty * 8 + 4];
            *(float4*)&bb[0] = *(const float4*)&Bs[kk][tx * 4];
#pragma unroll
            for (int i = 0; i < 8; i++)
#pragma unroll
                for (int j = 0; j < 4; j++)
                    acc[i][j] = fmaf(a[i], bb[j], acc[i][j]);
        }
        __syncthreads();
    }

    float bj[4];
#pragma unroll
    for (int j = 0; j < 4; j++) bj[j] = bias[col0 + tx * 4 + j];
#pragma unroll
    for (int i = 0; i < 8; i++) {
        int row = row0 + ty * 8 + i;
        float4 v;
        v.x = acc[i][0] + bj[0];
        v.y = acc[i][1] + bj[1];
        v.z = acc[i][2] + bj[2];
        v.w = acc[i][3] + bj[3];
        if (res) {
            float4 r = *(const float4*)(res + (size_t)row * N + col0 + tx * 4);
            v.x += r.x; v.y += r.y; v.z += r.z; v.w += r.w;
        }
        if (doRelu) {
            v.x = fmaxf(v.x, 0.f); v.y = fmaxf(v.y, 0.f);
            v.z = fmaxf(v.z, 0.f); v.w = fmaxf(v.w, 0.f);
        }
        *(float4*)(C + (size_t)row * N + col0 + tx * 4) = v;
    }
}

// ---------------- flash-style masked attention ----------------
// grid (L/128, H, B), 128 threads, one query row per thread, 32-key tiles.
__global__ void __launch_bounds__(128) attn_kernel(
    const float* __restrict__ qkv, float* __restrict__ ao,
    const int* __restrict__ lengths) {
    __shared__ float Ks[32][36];   // stride 36: float4-aligned rows
    __shared__ float Vs[32][36];
    __shared__ float Ss[128][33];  // per-thread score staging (conflict-free)
    const int b = blockIdx.z, h = blockIdx.y;
    const int t = threadIdx.x;
    const int q = blockIdx.x * 128 + t;
    const int len = lengths[b];
    const float scale = 0.17677669529663687f;  // 1/sqrt(32)
    const float* base = qkv + (size_t)b * L_ * 768;

    float qv[32];
    {
        const float4* qp = (const float4*)(base + (size_t)q * 768 + h * 32);
#pragma unroll
        for (int i = 0; i < 8; i++) *(float4*)&qv[i * 4] = qp[i];
    }
    float o[32];
#pragma unroll
    for (int i = 0; i < 32; i++) o[i] = 0.f;
    float m = -1e30f, lsum = 0.f;

    const int lr = t >> 2;        // key row 0..31
    const int lc = (t & 3) * 8;   // col chunk 0,8,16,24

    for (int kt = 0; kt < len; kt += 32) {
        // cooperative K/V tile load
        {
            const float* kp = base + (size_t)(kt + lr) * 768 + 256 + h * 32 + lc;
            const float* vp = kp + 256;
            float4 k0 = *(const float4*)kp, k1 = *(const float4*)(kp + 4);
            float4 v0 = *(const float4*)vp, v1 = *(const float4*)(vp + 4);
            Ks[lr][lc + 0] = k0.x; Ks[lr][lc + 1] = k0.y;
            Ks[lr][lc + 2] = k0.z; Ks[lr][lc + 3] = k0.w;
            Ks[lr][lc + 4] = k1.x; Ks[lr][lc + 5] = k1.y;
            Ks[lr][lc + 6] = k1.z; Ks[lr][lc + 7] = k1.w;
            Vs[lr][lc + 0] = v0.x; Vs[lr][lc + 1] = v0.y;
            Vs[lr][lc + 2] = v0.z; Vs[lr][lc + 3] = v0.w;
            Vs[lr][lc + 4] = v1.x; Vs[lr][lc + 5] = v1.y;
            Vs[lr][lc + 6] = v1.z; Vs[lr][lc + 7] = v1.w;
        }
        __syncthreads();

        // pass 1: scores + tile max
        float tmax = -1e30f;
#pragma unroll 4
        for (int j = 0; j < 32; j++) {
            float a0 = 0.f, a1 = 0.f, a2 = 0.f, a3 = 0.f;
#pragma unroll
            for (int d4 = 0; d4 < 8; d4++) {
                float4 kk = *(const float4*)&Ks[j][d4 * 4];
                a0 = fmaf(qv[d4 * 4 + 0], kk.x, a0);
                a1 = fmaf(qv[d4 * 4 + 1], kk.y, a1);
                a2 = fmaf(qv[d4 * 4 + 2], kk.z, a2);
                a3 = fmaf(qv[d4 * 4 + 3], kk.w, a3);
            }
            float s = (a0 + a1) + (a2 + a3);
            s = (kt + j < len) ? s * scale : -1e30f;
            Ss[t][j] = s;
            tmax = fmaxf(tmax, s);
        }

        // online softmax rescale
        float newm = fmaxf(m, tmax);
        float corr = __expf(m - newm);
        lsum *= corr;
#pragma unroll
        for (int i = 0; i < 32; i++) o[i] *= corr;

        // pass 2: accumulate P @ V
#pragma unroll 4
        for (int j = 0; j < 32; j++) {
            float p = __expf(Ss[t][j] - newm);
            lsum += p;
#pragma unroll
            for (int d4 = 0; d4 < 8; d4++) {
                float4 vv = *(const float4*)&Vs[j][d4 * 4];
                o[d4 * 4 + 0] = fmaf(p, vv.x, o[d4 * 4 + 0]);
                o[d4 * 4 + 1] = fmaf(p, vv.y, o[d4 * 4 + 1]);
                o[d4 * 4 + 2] = fmaf(p, vv.z, o[d4 * 4 + 2]);
                o[d4 * 4 + 3] = fmaf(p, vv.w, o[d4 * 4 + 3]);
            }
        }
        m = newm;
        __syncthreads();
    }

    float inv = 1.f / lsum;
    float* op = ao + (size_t)(b * L_ + q) * D_ + h * 32;
#pragma unroll
    for (int i = 0; i < 8; i++) {
        float4 v;
        v.x = o[i * 4 + 0] * inv; v.y = o[i * 4 + 1] * inv;
        v.z = o[i * 4 + 2] * inv; v.w = o[i * 4 + 3] * inv;
        *(float4*)&op[i * 4] = v;
    }
}

// ---------------- readout ----------------
__global__ void graph_out_kernel(const float* __restrict__ x,
                                 const int* __restrict__ lengths,
                                 float* __restrict__ out) {
    int b = blockIdx.x, d = threadIdx.x;
    int len = lengths[b];
    float s = 0.f;
    for (int l = 0; l < len; l++) s += x[((size_t)b * L_ + l) * D_ + d];
    int cnt = len > 1 ? len : 1;
    out[b * D_ + d] = s / (float)cnt;
}

__global__ void node_out_kernel(const float* __restrict__ x,
                                const int* __restrict__ lengths,
                                float* __restrict__ out) {
    int row = blockIdx.x, d = threadIdx.x;
    int b = row >> 10, l = row & 1023;
    float v = (l < lengths[b]) ? x[(size_t)row * D_ + d] : 0.f;
    out[(size_t)row * D_ + d] = v;
}

// ---------------- launch ----------------
extern "C" void kernel_launch(void* const* d_in, const int* in_sizes, int n_in,
                              void* d_out, int out_size) {
    const int*   ut      = (const int*)d_in[0];
    const int*   lengths = (const int*)d_in[1];
    const float* emb     = (const float*)d_in[2];
    const float* wqkv    = (const float*)d_in[3];
    const float* bqkv    = (const float*)d_in[4];
    const float* wo      = (const float*)d_in[5];
    const float* bo      = (const float*)d_in[6];
    const float* wlin    = (const float*)d_in[7];
    const float* blin    = (const float*)d_in[8];
    float* out = (float*)d_out;

    float *x, *qkvb, *aob, *h1b;
    cudaGetSymbolAddress((void**)&x, g_x);
    cudaGetSymbolAddress((void**)&qkvb, g_qkv);
    cudaGetSymbolAddress((void**)&aob, g_ao);
    cudaGetSymbolAddress((void**)&h1b, g_h1);

    embed_kernel<<<M_, 256>>>(ut, emb, x);

    for (int i = 0; i < NL_; i++) {
        // qkv = x @ Wqkv^T + bqkv   [16384,768]
        gemm_kernel<<<dim3(768 / 64, M_ / 128), 256>>>(
            x, wqkv + (size_t)i * 3 * D_ * D_, bqkv + (size_t)i * 3 * D_,
            nullptr, qkvb, 3 * D_, D_, 0);
        // masked multi-head attention
        attn_kernel<<<dim3(L_ / 128, H_, B_), 128>>>(qkvb, aob, lengths);
        // h1 = ao @ Wo^T + bo + x (residual)
        gemm_kernel<<<dim3(D_ / 64, M_ / 128), 256>>>(
            aob, wo + (size_t)i * D_ * D_, bo + (size_t)i * D_,
            x, h1b, D_, D_, 0);
        // x = relu?(h1 @ Wlin^T + blin)
        gemm_kernel<<<dim3(D_ / 64, M_ / 128), 256>>>(
            h1b, wlin + (size_t)i * D_ * D_, blin + (size_t)i * D_,
            nullptr, x, D_, D_, (i < NL_ - 1) ? 1 : 0);
    }

    graph_out_kernel<<<B_, 256>>>(x, lengths, out);
    node_out_kernel<<<M_, 256>>>(x, lengths, out + B_ * D_);
}

// round 2
// speedup vs baseline: 1.7292x; 1.7292x over previous
#include <cuda_runtime.h>
#include <math.h>
#include <stdint.h>

#define B_  16
#define L_  1024
#define D_  256
#define H_  8
#define HD_ 32
#define NL_ 3
#define M_  (B_ * L_)   // 16384

// ---------------- scratch (no allocations allowed) ----------------
__device__ float g_x[M_ * D_];
__device__ float g_qkv[M_ * 3 * D_];
__device__ float g_ao[M_ * D_];
__device__ float g_h1[M_ * D_];
__device__ float g_red[B_ * 8 * D_];

// ---------------- helpers ----------------
__device__ __forceinline__ uint32_t f2tf32(float x) {
    uint32_t u;
    asm("cvt.rna.tf32.f32 %0, %1;" : "=r"(u) : "f"(x));
    return u;
}

__device__ __forceinline__ void mma_tf32(float c[4], const uint32_t a[4],
                                         const uint32_t b[2]) {
    asm volatile(
        "mma.sync.aligned.m16n8k8.row.col.f32.tf32.tf32.f32 "
        "{%0,%1,%2,%3}, {%4,%5,%6,%7}, {%8,%9}, {%0,%1,%2,%3};\n"
        : "+f"(c[0]), "+f"(c[1]), "+f"(c[2]), "+f"(c[3])
        : "r"(a[0]), "r"(a[1]), "r"(a[2]), "r"(a[3]), "r"(b[0]), "r"(b[1]));
}

// ---------------- embedding gather ----------------
__global__ void embed_kernel(const int* __restrict__ ut,
                             const float* __restrict__ emb,
                             float* __restrict__ x) {
    int row = blockIdx.x;
    int d = threadIdx.x;
    x[(size_t)row * D_ + d] = emb[(size_t)ut[row] * D_ + d];
}

// ---------------- tf32 tensor-core GEMM ----------------
// C[M,N] = A[M,K] @ W[N,K]^T + bias (+res) (relu)
// BM=128, BN=64, BK=32, 256 threads = 8 warps (4 in M x 2 in N),
// warp tile 32x32 via m16n8k8 (2 M-tiles x 4 N-tiles x 4 k-steps).
// Early-exit for row-blocks entirely past lengths[b] (ragged batch).
#define GPAD 36
__global__ void __launch_bounds__(256) gemm_tc_kernel(
    const float* __restrict__ A, const float* __restrict__ W,
    const float* __restrict__ bias, const float* __restrict__ res,
    float* __restrict__ C, const int* __restrict__ lengths,
    int N, int K, int doRelu) {
    const int row0 = blockIdx.y * 128;
    {   // ragged early exit: rows >= len feed only rows >= len (masked at output)
        int b = row0 >> 10, l0 = row0 & 1023;
        if (l0 >= lengths[b]) return;
    }
    __shared__ float As[128 * GPAD];
    __shared__ float Bs[64 * GPAD];
    const int tid = threadIdx.x;
    const int warp = tid >> 5, lane = tid & 31;
    const int g = lane >> 2, t4 = lane & 3;
    const int wm = (warp & 3) * 32;   // warp M offset in tile
    const int wn = (warp >> 2) * 32;  // warp N offset in tile
    const int col0 = blockIdx.x * 64;

    // global->smem mapping
    const int arow = tid >> 1, acol0 = (tid & 1) * 16;
    const int brow = tid >> 2, bcol0 = (tid & 3) * 8;

    float acc[2][4][4];
#pragma unroll
    for (int mi = 0; mi < 2; mi++)
#pragma unroll
        for (int ni = 0; ni < 4; ni++)
#pragma unroll
            for (int j = 0; j < 4; j++) acc[mi][ni][j] = 0.f;

    for (int kt = 0; kt < K; kt += 32) {
        {   // A tile: 128 x 32, converted to tf32 bits
            const float* ap = A + (size_t)(row0 + arow) * K + kt + acol0;
#pragma unroll
            for (int i = 0; i < 4; i++) {
                float4 v = *(const float4*)(ap + i * 4);
                uint4 w;
                w.x = f2tf32(v.x); w.y = f2tf32(v.y);
                w.z = f2tf32(v.z); w.w = f2tf32(v.w);
                *(uint4*)&As[arow * GPAD + acol0 + i * 4] = w;
            }
        }
        {   // W tile: 64 x 32
            const float* wp = W + (size_t)(col0 + brow) * K + kt + bcol0;
#pragma unroll
            for (int i = 0; i < 2; i++) {
                float4 v = *(const float4*)(wp + i * 4);
                uint4 w;
                w.x = f2tf32(v.x); w.y = f2tf32(v.y);
                w.z = f2tf32(v.z); w.w = f2tf32(v.w);
                *(uint4*)&Bs[brow * GPAD + bcol0 + i * 4] = w;
            }
        }
        __syncthreads();

#pragma unroll
        for (int ks = 0; ks < 4; ks++) {
            const int k0 = ks * 8;
            uint32_t a[2][4];
#pragma unroll
            for (int mi = 0; mi < 2; mi++) {
                int r = wm + mi * 16;
                a[mi][0] = __float_as_uint(As[(r + g) * GPAD + k0 + t4]);
                a[mi][1] = __float_as_uint(As[(r + g + 8) * GPAD + k0 + t4]);
                a[mi][2] = __float_as_uint(As[(r + g) * GPAD + k0 + t4 + 4]);
                a[mi][3] = __float_as_uint(As[(r + g + 8) * GPAD + k0 + t4 + 4]);
            }
            uint32_t bf[4][2];
#pragma unroll
            for (int ni = 0; ni < 4; ni++) {
                int c = wn + ni * 8;
                bf[ni][0] = __float_as_uint(Bs[(c + g) * GPAD + k0 + t4]);
                bf[ni][1] = __float_as_uint(Bs[(c + g) * GPAD + k0 + t4 + 4]);
            }
#pragma unroll
            for (int mi = 0; mi < 2; mi++)
#pragma unroll
                for (int ni = 0; ni < 4; ni++)
                    mma_tf32(acc[mi][ni], a[mi], bf[ni]);
        }
        __syncthreads();
    }

    // epilogue: c0,c1 -> (row g, cols 2t4,2t4+1), c2,c3 -> row g+8
#pragma unroll
    for (int ni = 0; ni < 4; ni++) {
        int c = col0 + wn + ni * 8 + 2 * t4;
        float b0 = bias[c], b1 = bias[c + 1];
#pragma unroll
        for (int mi = 0; mi < 2; mi++) {
#pragma unroll
            for (int half = 0; half < 2; half++) {
                int r = row0 + wm + mi * 16 + g + half * 8;
                float v0 = acc[mi][ni][half * 2 + 0] + b0;
                float v1 = acc[mi][ni][half * 2 + 1] + b1;
                if (res) {
                    float2 rr = *(const float2*)(res + (size_t)r * N + c);
                    v0 += rr.x; v1 += rr.y;
                }
                if (doRelu) { v0 = fmaxf(v0, 0.f); v1 = fmaxf(v1, 0.f); }
                float2 o; o.x = v0; o.y = v1;
                *(float2*)(C + (size_t)r * N + c) = o;
            }
        }
    }
}

// ---------------- flash-style masked attention (fp32) ----------------
__global__ void __launch_bounds__(128) attn_kernel(
    const float* __restrict__ qkv, float* __restrict__ ao,
    const int* __restrict__ lengths) {
    const int b = blockIdx.z, h = blockIdx.y;
    const int len = lengths[b];
    if ((int)blockIdx.x * 128 >= len) return;  // ragged query early exit
    __shared__ float Ks[32][36];
    __shared__ float Vs[32][36];
    __shared__ float Ss[128][33];
    const int t = threadIdx.x;
    const int q = blockIdx.x * 128 + t;
    const float scale = 0.17677669529663687f;  // 1/sqrt(32)
    const float* base = qkv + (size_t)b * L_ * 768;

    float qv[32];
    {
        const float4* qp = (const float4*)(base + (size_t)q * 768 + h * 32);
#pragma unroll
        for (int i = 0; i < 8; i++) *(float4*)&qv[i * 4] = qp[i];
    }
    float o[32];
#pragma unroll
    for (int i = 0; i < 32; i++) o[i] = 0.f;
    float m = -1e30f, lsum = 0.f;

    const int lr = t >> 2;
    const int lc = (t & 3) * 8;

    for (int kt = 0; kt < len; kt += 32) {
        {
            const float* kp = base + (size_t)(kt + lr) * 768 + 256 + h * 32 + lc;
            const float* vp = kp + 256;
            float4 k0 = *(const float4*)kp, k1 = *(const float4*)(kp + 4);
            float4 v0 = *(const float4*)vp, v1 = *(const float4*)(vp + 4);
            Ks[lr][lc + 0] = k0.x; Ks[lr][lc + 1] = k0.y;
            Ks[lr][lc + 2] = k0.z; Ks[lr][lc + 3] = k0.w;
            Ks[lr][lc + 4] = k1.x; Ks[lr][lc + 5] = k1.y;
            Ks[lr][lc + 6] = k1.z; Ks[lr][lc + 7] = k1.w;
            Vs[lr][lc + 0] = v0.x; Vs[lr][lc + 1] = v0.y;
            Vs[lr][lc + 2] = v0.z; Vs[lr][lc + 3] = v0.w;
            Vs[lr][lc + 4] = v1.x; Vs[lr][lc + 5] = v1.y;
            Vs[lr][lc + 6] = v1.z; Vs[lr][lc + 7] = v1.w;
        }
        __syncthreads();

        float tmax = -1e30f;
#pragma unroll 4
        for (int j = 0; j < 32; j++) {
            float a0 = 0.f, a1 = 0.f, a2 = 0.f, a3 = 0.f;
#pragma unroll
            for (int d4 = 0; d4 < 8; d4++) {
                float4 kk = *(const float4*)&Ks[j][d4 * 4];
                a0 = fmaf(qv[d4 * 4 + 0], kk.x, a0);
                a1 = fmaf(qv[d4 * 4 + 1], kk.y, a1);
                a2 = fmaf(qv[d4 * 4 + 2], kk.z, a2);
                a3 = fmaf(qv[d4 * 4 + 3], kk.w, a3);
            }
            float s = (a0 + a1) + (a2 + a3);
            s = (kt + j < len) ? s * scale : -1e30f;
            Ss[t][j] = s;
            tmax = fmaxf(tmax, s);
        }

        float newm = fmaxf(m, tmax);
        float corr = __expf(m - newm);
        lsum *= corr;
#pragma unroll
        for (int i = 0; i < 32; i++) o[i] *= corr;

#pragma unroll 4
        for (int j = 0; j < 32; j++) {
            float p = __expf(Ss[t][j] - newm);
            lsum += p;
#pragma unroll
            for (int d4 = 0; d4 < 8; d4++) {
                float4 vv = *(const float4*)&Vs[j][d4 * 4];
                o[d4 * 4 + 0] = fmaf(p, vv.x, o[d4 * 4 + 0]);
                o[d4 * 4 + 1] = fmaf(p, vv.y, o[d4 * 4 + 1]);
                o[d4 * 4 + 2] = fmaf(p, vv.z, o[d4 * 4 + 2]);
                o[d4 * 4 + 3] = fmaf(p, vv.w, o[d4 * 4 + 3]);
            }
        }
        m = newm;
        __syncthreads();
    }

    float inv = 1.f / lsum;
    float* op = ao + (size_t)(b * L_ + q) * D_ + h * 32;
#pragma unroll
    for (int i = 0; i < 8; i++) {
        float4 v;
        v.x = o[i * 4 + 0] * inv; v.y = o[i * 4 + 1] * inv;
        v.z = o[i * 4 + 2] * inv; v.w = o[i * 4 + 3] * inv;
        *(float4*)&op[i * 4] = v;
    }
}

// ---------------- readout (deterministic two-stage mean) ----------------
__global__ void graph_partial_kernel(const float* __restrict__ x,
                                     const int* __restrict__ lengths,
                                     float* __restrict__ red) {
    int chunk = blockIdx.x, b = blockIdx.y, d = threadIdx.x;
    int len = lengths[b];
    int l0 = chunk * 128;
    int l1 = min(l0 + 128, len);
    float s = 0.f;
    for (int l = l0; l < l1; l++) s += x[((size_t)b * L_ + l) * D_ + d];
    red[((size_t)b * 8 + chunk) * D_ + d] = s;
}

__global__ void graph_final_kernel(const float* __restrict__ red,
                                   const int* __restrict__ lengths,
                                   float* __restrict__ out) {
    int b = blockIdx.x, d = threadIdx.x;
    float s = 0.f;
#pragma unroll
    for (int c = 0; c < 8; c++) s += red[((size_t)b * 8 + c) * D_ + d];
    int cnt = lengths[b] > 1 ? lengths[b] : 1;
    out[b * D_ + d] = s / (float)cnt;
}

__global__ void node_out_kernel(const float* __restrict__ x,
                                const int* __restrict__ lengths,
                                float* __restrict__ out) {
    int row = blockIdx.x, d = threadIdx.x;
    int b = row >> 10, l = row & 1023;
    float v = (l < lengths[b]) ? x[(size_t)row * D_ + d] : 0.f;
    out[(size_t)row * D_ + d] = v;
}

// ---------------- launch ----------------
extern "C" void kernel_launch(void* const* d_in, const int* in_sizes, int n_in,
                              void* d_out, int out_size) {
    const int*   ut      = (const int*)d_in[0];
    const int*   lengths = (const int*)d_in[1];
    const float* emb     = (const float*)d_in[2];
    const float* wqkv    = (const float*)d_in[3];
    const float* bqkv    = (const float*)d_in[4];
    const float* wo      = (const float*)d_in[5];
    const float* bo      = (const float*)d_in[6];
    const float* wlin    = (const float*)d_in[7];
    const float* blin    = (const float*)d_in[8];
    float* out = (float*)d_out;

    float *x, *qkvb, *aob, *h1b, *redb;
    cudaGetSymbolAddress((void**)&x, g_x);
    cudaGetSymbolAddress((void**)&qkvb, g_qkv);
    cudaGetSymbolAddress((void**)&aob, g_ao);
    cudaGetSymbolAddress((void**)&h1b, g_h1);
    cudaGetSymbolAddress((void**)&redb, g_red);

    embed_kernel<<<M_, 256>>>(ut, emb, x);

    for (int i = 0; i < NL_; i++) {
        gemm_tc_kernel<<<dim3(768 / 64, M_ / 128), 256>>>(
            x, wqkv + (size_t)i * 3 * D_ * D_, bqkv + (size_t)i * 3 * D_,
            nullptr, qkvb, lengths, 3 * D_, D_, 0);
        attn_kernel<<<dim3(L_ / 128, H_, B_), 128>>>(qkvb, aob, lengths);
        gemm_tc_kernel<<<dim3(D_ / 64, M_ / 128), 256>>>(
            aob, wo + (size_t)i * D_ * D_, bo + (size_t)i * D_,
            x, h1b, lengths, D_, D_, 0);
        gemm_tc_kernel<<<dim3(D_ / 64, M_ / 128), 256>>>(
            h1b, wlin + (size_t)i * D_ * D_, blin + (size_t)i * D_,
            nullptr, x, lengths, D_, D_, (i < NL_ - 1) ? 1 : 0);
    }

    graph_partial_kernel<<<dim3(8, B_), 256>>>(x, lengths, redb);
    graph_final_kernel<<<B_, 256>>>(redb, lengths, out);
    node_out_kernel<<<M_, 256>>>(x, lengths, out + B_ * D_);
}

// round 3
// speedup vs baseline: 3.5306x; 2.0417x over previous
#include <cuda_runtime.h>
#include <math.h>
#include <stdint.h>

#define B_  16
#define L_  1024
#define D_  256
#define H_  8
#define NL_ 3
#define M_  (B_ * L_)   // 16384

// ---------------- scratch ----------------
__device__ float g_x[M_ * D_];
__device__ float g_qkv[M_ * 3 * D_];
__device__ float g_ao[M_ * D_];
__device__ float g_h1[M_ * D_];
__device__ float g_red[B_ * 8 * D_];

// ---------------- helpers ----------------
__device__ __forceinline__ uint32_t f2tf32(float x) {
    uint32_t u;
    asm("cvt.rna.tf32.f32 %0, %1;" : "=r"(u) : "f"(x));
    return u;
}

__device__ __forceinline__ void mma_tf32(float c[4], const uint32_t a[4],
                                         const uint32_t b[2]) {
    asm volatile(
        "mma.sync.aligned.m16n8k8.row.col.f32.tf32.tf32.f32 "
        "{%0,%1,%2,%3}, {%4,%5,%6,%7}, {%8,%9}, {%0,%1,%2,%3};\n"
        : "+f"(c[0]), "+f"(c[1]), "+f"(c[2]), "+f"(c[3])
        : "r"(a[0]), "r"(a[1]), "r"(a[2]), "r"(a[3]), "r"(b[0]), "r"(b[1]));
}

// ---------------- embedding gather ----------------
__global__ void embed_kernel(const int* __restrict__ ut,
                             const float* __restrict__ emb,
                             float* __restrict__ x) {
    int row = blockIdx.x;
    int d = threadIdx.x;
    x[(size_t)row * D_ + d] = emb[(size_t)ut[row] * D_ + d];
}

// ---------------- tf32 tensor-core GEMM with register prefetch ----------------
// C[M,N] = A[M,K] @ W[N,K]^T + bias (+res) (relu); ragged row-block early exit.
#define GPAD 36
__global__ void __launch_bounds__(256) gemm_tc_kernel(
    const float* __restrict__ A, const float* __restrict__ W,
    const float* __restrict__ bias, const float* __restrict__ res,
    float* __restrict__ C, const int* __restrict__ lengths,
    int N, int K, int doRelu) {
    const int row0 = blockIdx.y * 128;
    {
        int b = row0 >> 10, l0 = row0 & 1023;
        if (l0 >= lengths[b]) return;
    }
    __shared__ float As[128 * GPAD];
    __shared__ float Bs[64 * GPAD];
    const int tid = threadIdx.x;
    const int warp = tid >> 5, lane = tid & 31;
    const int g = lane >> 2, t4 = lane & 3;
    const int wm = (warp & 3) * 32;
    const int wn = (warp >> 2) * 32;
    const int col0 = blockIdx.x * 64;

    const int arow = tid >> 1, acol0 = (tid & 1) * 16;
    const int brow = tid >> 2, bcol0 = (tid & 3) * 8;

    float acc[2][4][4];
#pragma unroll
    for (int mi = 0; mi < 2; mi++)
#pragma unroll
        for (int ni = 0; ni < 4; ni++)
#pragma unroll
            for (int j = 0; j < 4; j++) acc[mi][ni][j] = 0.f;

    const float* ap = A + (size_t)(row0 + arow) * K + acol0;
    const float* wp = W + (size_t)(col0 + brow) * K + bcol0;

    float4 ra[4], rb[2];
#pragma unroll
    for (int i = 0; i < 4; i++) ra[i] = *(const float4*)(ap + i * 4);
#pragma unroll
    for (int i = 0; i < 2; i++) rb[i] = *(const float4*)(wp + i * 4);

    for (int kt = 0; kt < K; kt += 32) {
#pragma unroll
        for (int i = 0; i < 4; i++) {
            uint4 w4;
            w4.x = f2tf32(ra[i].x); w4.y = f2tf32(ra[i].y);
            w4.z = f2tf32(ra[i].z); w4.w = f2tf32(ra[i].w);
            *(uint4*)&As[arow * GPAD + acol0 + i * 4] = w4;
        }
#pragma unroll
        for (int i = 0; i < 2; i++) {
            uint4 w4;
            w4.x = f2tf32(rb[i].x); w4.y = f2tf32(rb[i].y);
            w4.z = f2tf32(rb[i].z); w4.w = f2tf32(rb[i].w);
            *(uint4*)&Bs[brow * GPAD + bcol0 + i * 4] = w4;
        }
        __syncthreads();

        if (kt + 32 < K) {   // prefetch next tile while mma runs
#pragma unroll
            for (int i = 0; i < 4; i++) ra[i] = *(const float4*)(ap + kt + 32 + i * 4);
#pragma unroll
            for (int i = 0; i < 2; i++) rb[i] = *(const float4*)(wp + kt + 32 + i * 4);
        }

#pragma unroll
        for (int ks = 0; ks < 4; ks++) {
            const int k0 = ks * 8;
            uint32_t a[2][4];
#pragma unroll
            for (int mi = 0; mi < 2; mi++) {
                int r = wm + mi * 16;
                a[mi][0] = __float_as_uint(As[(r + g) * GPAD + k0 + t4]);
                a[mi][1] = __float_as_uint(As[(r + g + 8) * GPAD + k0 + t4]);
                a[mi][2] = __float_as_uint(As[(r + g) * GPAD + k0 + t4 + 4]);
                a[mi][3] = __float_as_uint(As[(r + g + 8) * GPAD + k0 + t4 + 4]);
            }
            uint32_t bf[4][2];
#pragma unroll
            for (int ni = 0; ni < 4; ni++) {
                int c = wn + ni * 8;
                bf[ni][0] = __float_as_uint(Bs[(c + g) * GPAD + k0 + t4]);
                bf[ni][1] = __float_as_uint(Bs[(c + g) * GPAD + k0 + t4 + 4]);
            }
#pragma unroll
            for (int mi = 0; mi < 2; mi++)
#pragma unroll
                for (int ni = 0; ni < 4; ni++)
                    mma_tf32(acc[mi][ni], a[mi], bf[ni]);
        }
        __syncthreads();
    }

#pragma unroll
    for (int ni = 0; ni < 4; ni++) {
        int c = col0 + wn + ni * 8 + 2 * t4;
        float b0 = bias[c], b1 = bias[c + 1];
#pragma unroll
        for (int mi = 0; mi < 2; mi++) {
#pragma unroll
            for (int half = 0; half < 2; half++) {
                int r = row0 + wm + mi * 16 + g + half * 8;
                float v0 = acc[mi][ni][half * 2 + 0] + b0;
                float v1 = acc[mi][ni][half * 2 + 1] + b1;
                if (res) {
                    float2 rr = *(const float2*)(res + (size_t)r * N + c);
                    v0 += rr.x; v1 += rr.y;
                }
                if (doRelu) { v0 = fmaxf(v0, 0.f); v1 = fmaxf(v1, 0.f); }
                float2 o; o.x = v0; o.y = v1;
                *(float2*)(C + (size_t)r * N + c) = o;
            }
        }
    }
}

// ---------------- tensor-core masked flash attention (tf32 mma, fp32 softmax) ---
// block = 64 queries, 4 warps x 16 queries; key tiles of 64.
#define QPAD 36
#define KPAD 36
#define VPAD 40
#define PPAD 72
__global__ void __launch_bounds__(128) attn_tc_kernel(
    const float* __restrict__ qkv, float* __restrict__ ao,
    const int* __restrict__ lengths) {
    const int b = blockIdx.z, h = blockIdx.y;
    const int len = lengths[b];
    const int q0 = blockIdx.x * 64;
    if (q0 >= len) return;

    __shared__ float Qs[64 * QPAD];
    __shared__ float Ks[64 * KPAD];
    __shared__ float Vs[64 * VPAD];
    __shared__ float Ps[64 * PPAD];

    const int tid = threadIdx.x, w = tid >> 5, lane = tid & 31;
    const int g = lane >> 2, t4 = lane & 3;
    const int wq = w * 16;
    const float scale = 0.17677669529663687f;  // 1/sqrt(32)
    const float* base = qkv + (size_t)b * L_ * 768;

    // ---- load Q tile (64 x 32) as tf32 into smem ----
#pragma unroll
    for (int i = 0; i < 4; i++) {
        int c = tid + i * 128;          // 0..511
        int row = c >> 3, ch = (c & 7) * 4;
        float4 v = *(const float4*)(base + (size_t)(q0 + row) * 768 + h * 32 + ch);
        uint4 u;
        u.x = f2tf32(v.x); u.y = f2tf32(v.y);
        u.z = f2tf32(v.z); u.w = f2tf32(v.w);
        *(uint4*)&Qs[row * QPAD + ch] = u;
    }
    __syncthreads();

    // ---- Q A-fragments, register-resident for the whole kernel ----
    uint32_t qa[4][4];
#pragma unroll
    for (int kc = 0; kc < 4; kc++) {
        qa[kc][0] = __float_as_uint(Qs[(wq + g) * QPAD + kc * 8 + t4]);
        qa[kc][1] = __float_as_uint(Qs[(wq + g + 8) * QPAD + kc * 8 + t4]);
        qa[kc][2] = __float_as_uint(Qs[(wq + g) * QPAD + kc * 8 + t4 + 4]);
        qa[kc][3] = __float_as_uint(Qs[(wq + g + 8) * QPAD + kc * 8 + t4 + 4]);
    }

    float o[4][4];
#pragma unroll
    for (int nv = 0; nv < 4; nv++)
#pragma unroll
        for (int j = 0; j < 4; j++) o[nv][j] = 0.f;
    float m0 = -1e30f, m1 = -1e30f, ls0 = 0.f, ls1 = 0.f;

    for (int kt = 0; kt < len; kt += 64) {
        __syncthreads();  // all warps done reading Ks/Vs of prior tile
        // ---- load K,V tiles (64 x 32 each) as tf32 ----
#pragma unroll
        for (int i = 0; i < 4; i++) {
            int c = tid + i * 128;
            int row = c >> 3, ch = (c & 7) * 4;
            const float* kp = base + (size_t)(kt + row) * 768 + 256 + h * 32 + ch;
            float4 kv = *(const float4*)kp;
            float4 vv = *(const float4*)(kp + 256);
            uint4 ku, vu;
            ku.x = f2tf32(kv.x); ku.y = f2tf32(kv.y);
            ku.z = f2tf32(kv.z); ku.w = f2tf32(kv.w);
            vu.x = f2tf32(vv.x); vu.y = f2tf32(vv.y);
            vu.z = f2tf32(vv.z); vu.w = f2tf32(vv.w);
            *(uint4*)&Ks[row * KPAD + ch] = ku;
            *(uint4*)&Vs[row * VPAD + ch] = vu;
        }
        __syncthreads();

        // ---- S = Q @ K^T : 8 n-tiles of 8 keys ----
        float sc[8][4];
#pragma unroll
        for (int n = 0; n < 8; n++) {
            sc[n][0] = sc[n][1] = sc[n][2] = sc[n][3] = 0.f;
#pragma unroll
            for (int kc = 0; kc < 4; kc++) {
                uint32_t bb[2];
                bb[0] = __float_as_uint(Ks[(n * 8 + g) * KPAD + kc * 8 + t4]);
                bb[1] = __float_as_uint(Ks[(n * 8 + g) * KPAD + kc * 8 + t4 + 4]);
                mma_tf32(sc[n], qa[kc], bb);
            }
        }

        // ---- scale + key mask + row max ----
        float rmax0 = -1e30f, rmax1 = -1e30f;
#pragma unroll
        for (int n = 0; n < 8; n++) {
            int c0 = kt + n * 8 + 2 * t4;
            bool v0 = c0 < len, v1 = (c0 + 1) < len;
            sc[n][0] = v0 ? sc[n][0] * scale : -1e30f;
            sc[n][1] = v1 ? sc[n][1] * scale : -1e30f;
            sc[n][2] = v0 ? sc[n][2] * scale : -1e30f;
            sc[n][3] = v1 ? sc[n][3] * scale : -1e30f;
            rmax0 = fmaxf(rmax0, fmaxf(sc[n][0], sc[n][1]));
            rmax1 = fmaxf(rmax1, fmaxf(sc[n][2], sc[n][3]));
        }
        rmax0 = fmaxf(rmax0, __shfl_xor_sync(0xffffffffu, rmax0, 1));
        rmax0 = fmaxf(rmax0, __shfl_xor_sync(0xffffffffu, rmax0, 2));
        rmax1 = fmaxf(rmax1, __shfl_xor_sync(0xffffffffu, rmax1, 1));
        rmax1 = fmaxf(rmax1, __shfl_xor_sync(0xffffffffu, rmax1, 2));

        float nm0 = fmaxf(m0, rmax0), nm1 = fmaxf(m1, rmax1);
        float cr0 = __expf(m0 - nm0), cr1 = __expf(m1 - nm1);
        ls0 *= cr0; ls1 *= cr1;
#pragma unroll
        for (int nv = 0; nv < 4; nv++) {
            o[nv][0] *= cr0; o[nv][1] *= cr0;
            o[nv][2] *= cr1; o[nv][3] *= cr1;
        }
        m0 = nm0; m1 = nm1;

        // ---- exp -> P (tf32) into per-warp smem slab ----
#pragma unroll
        for (int n = 0; n < 8; n++) {
            float p0 = __expf(sc[n][0] - m0), p1 = __expf(sc[n][1] - m0);
            float p2 = __expf(sc[n][2] - m1), p3 = __expf(sc[n][3] - m1);
            ls0 += p0 + p1;
            ls1 += p2 + p3;
            float2 lo, hi;
            lo.x = __uint_as_float(f2tf32(p0)); lo.y = __uint_as_float(f2tf32(p1));
            hi.x = __uint_as_float(f2tf32(p2)); hi.y = __uint_as_float(f2tf32(p3));
            *(float2*)&Ps[(wq + g) * PPAD + n * 8 + 2 * t4] = lo;
            *(float2*)&Ps[(wq + g + 8) * PPAD + n * 8 + 2 * t4] = hi;
        }
        __syncwarp();

        // ---- O += P @ V : 8 k-chunks x 4 n-tiles ----
#pragma unroll
        for (int kc2 = 0; kc2 < 8; kc2++) {
            uint32_t pa[4];
            pa[0] = __float_as_uint(Ps[(wq + g) * PPAD + kc2 * 8 + t4]);
            pa[1] = __float_as_uint(Ps[(wq + g + 8) * PPAD + kc2 * 8 + t4]);
            pa[2] = __float_as_uint(Ps[(wq + g) * PPAD + kc2 * 8 + t4 + 4]);
            pa[3] = __float_as_uint(Ps[(wq + g + 8) * PPAD + kc2 * 8 + t4 + 4]);
#pragma unroll
            for (int nv = 0; nv < 4; nv++) {
                uint32_t vb[2];
                vb[0] = __float_as_uint(Vs[(kc2 * 8 + t4) * VPAD + nv * 8 + g]);
                vb[1] = __float_as_uint(Vs[(kc2 * 8 + t4 + 4) * VPAD + nv * 8 + g]);
                mma_tf32(o[nv], pa, vb);
            }
        }
        __syncwarp();
    }

    // ---- finalize: full row sums, normalize, write ----
    ls0 += __shfl_xor_sync(0xffffffffu, ls0, 1);
    ls0 += __shfl_xor_sync(0xffffffffu, ls0, 2);
    ls1 += __shfl_xor_sync(0xffffffffu, ls1, 1);
    ls1 += __shfl_xor_sync(0xffffffffu, ls1, 2);
    float i0 = 1.f / ls0, i1 = 1.f / ls1;

    const int r0 = q0 + wq + g;
    float* op0 = ao + (size_t)(b * L_ + r0) * D_ + h * 32;
    float* op1 = ao + (size_t)(b * L_ + r0 + 8) * D_ + h * 32;
#pragma unroll
    for (int nv = 0; nv < 4; nv++) {
        float2 lo, hi;
        lo.x = o[nv][0] * i0; lo.y = o[nv][1] * i0;
        hi.x = o[nv][2] * i1; hi.y = o[nv][3] * i1;
        *(float2*)(op0 + nv * 8 + 2 * t4) = lo;
        *(float2*)(op1 + nv * 8 + 2 * t4) = hi;
    }
}

// ---------------- readout ----------------
__global__ void graph_partial_kernel(const float* __restrict__ x,
                                     const int* __restrict__ lengths,
                                     float* __restrict__ red) {
    int chunk = blockIdx.x, b = blockIdx.y, d = threadIdx.x;
    int len = lengths[b];
    int l0 = chunk * 128;
    int l1 = min(l0 + 128, len);
    float s = 0.f;
    for (int l = l0; l < l1; l++) s += x[((size_t)b * L_ + l) * D_ + d];
    red[((size_t)b * 8 + chunk) * D_ + d] = s;
}

__global__ void graph_final_kernel(const float* __restrict__ red,
                                   const int* __restrict__ lengths,
                                   float* __restrict__ out) {
    int b = blockIdx.x, d = threadIdx.x;
    float s = 0.f;
#pragma unroll
    for (int c = 0; c < 8; c++) s += red[((size_t)b * 8 + c) * D_ + d];
    int cnt = lengths[b] > 1 ? lengths[b] : 1;
    out[b * D_ + d] = s / (float)cnt;
}

__global__ void node_out_kernel(const float* __restrict__ x,
                                const int* __restrict__ lengths,
                                float* __restrict__ out) {
    int row = blockIdx.x, d = threadIdx.x;
    int b = row >> 10, l = row & 1023;
    float v = (l < lengths[b]) ? x[(size_t)row * D_ + d] : 0.f;
    out[(size_t)row * D_ + d] = v;
}

// ---------------- launch ----------------
extern "C" void kernel_launch(void* const* d_in, const int* in_sizes, int n_in,
                              void* d_out, int out_size) {
    const int*   ut      = (const int*)d_in[0];
    const int*   lengths = (const int*)d_in[1];
    const float* emb     = (const float*)d_in[2];
    const float* wqkv    = (const float*)d_in[3];
    const float* bqkv    = (const float*)d_in[4];
    const float* wo      = (const float*)d_in[5];
    const float* bo      = (const float*)d_in[6];
    const float* wlin    = (const float*)d_in[7];
    const float* blin    = (const float*)d_in[8];
    float* out = (float*)d_out;

    float *x, *qkvb, *aob, *h1b, *redb;
    cudaGetSymbolAddress((void**)&x, g_x);
    cudaGetSymbolAddress((void**)&qkvb, g_qkv);
    cudaGetSymbolAddress((void**)&aob, g_ao);
    cudaGetSymbolAddress((void**)&h1b, g_h1);
    cudaGetSymbolAddress((void**)&redb, g_red);

    embed_kernel<<<M_, 256>>>(ut, emb, x);

    for (int i = 0; i < NL_; i++) {
        gemm_tc_kernel<<<dim3(768 / 64, M_ / 128), 256>>>(
            x, wqkv + (size_t)i * 3 * D_ * D_, bqkv + (size_t)i * 3 * D_,
            nullptr, qkvb, lengths, 3 * D_, D_, 0);
        attn_tc_kernel<<<dim3(L_ / 64, H_, B_), 128>>>(qkvb, aob, lengths);
        gemm_tc_kernel<<<dim3(D_ / 64, M_ / 128), 256>>>(
            aob, wo + (size_t)i * D_ * D_, bo + (size_t)i * D_,
            x, h1b, lengths, D_, D_, 0);
        gemm_tc_kernel<<<dim3(D_ / 64, M_ / 128), 256>>>(
            h1b, wlin + (size_t)i * D_ * D_, blin + (size_t)i * D_,
            nullptr, x, lengths, D_, D_, (i < NL_ - 1) ? 1 : 0);
    }

    graph_partial_kernel<<<dim3(8, B_), 256>>>(x, lengths, redb);
    graph_final_kernel<<<B_, 256>>>(redb, lengths, out);
    node_out_kernel<<<M_, 256>>>(x, lengths, out + B_ * D_);
}